// round 1
// baseline (speedup 1.0000x reference)
#include <cuda_runtime.h>
#include <math.h>
#include <stdint.h>

#define B 16
#define T 2048
#define D 512
#define C 512
#define KW 11
#define KHALF 5
#define THRESH 0.9f
#define MAXTOK 128

// ---------------- scratch (no allocation allowed) ----------------
__device__ float g_weff[KW * D];
__device__ float g_beff;
__device__ float g_q[KW * B * T];      // q[k][b][t] = dot(eouts[b,t,:], w_eff[k,:])
__device__ float g_anorm[B * T];       // alpha_norm
__device__ int   g_seg_s[B * MAXTOK];  // prev fire time (-1 for first token)
__device__ int   g_seg_e[B * MAXTOK];  // fire time of this token
__device__ float g_c0[B * MAXTOK];     // ak2 of previous fire (coef at seg_s)
__device__ float g_c1[B * MAXTOK];     // ak1 at seg_e
__device__ int   g_nf[B];              // number of fired tokens per batch

// ---------------- kernel 1: fold projection into conv weights ----------------
// one warp per (k,d) element; one extra warp for the bias term
__global__ void k_weff(const float* __restrict__ conv_w,
                       const float* __restrict__ conv_b,
                       const float* __restrict__ proj_w,
                       const float* __restrict__ proj_b) {
    int wid  = blockIdx.x * (blockDim.x >> 5) + (threadIdx.x >> 5);
    int lane = threadIdx.x & 31;
    if (wid < KW * D) {
        const float* row = conv_w + (size_t)wid * C;
        float s = 0.f;
        #pragma unroll 4
        for (int c = lane; c < C; c += 32) s += row[c] * proj_w[c];
        #pragma unroll
        for (int o = 16; o; o >>= 1) s += __shfl_down_sync(0xffffffffu, s, o);
        if (lane == 0) g_weff[wid] = s;
    } else if (wid == KW * D) {
        float s = 0.f;
        for (int c = lane; c < C; c += 32) s += conv_b[c] * proj_w[c];
        #pragma unroll
        for (int o = 16; o; o >>= 1) s += __shfl_down_sync(0xffffffffu, s, o);
        if (lane == 0) g_beff = s + proj_b[0];
    }
}

// ---------------- kernel 2a: per-timestep 11 dots (one pass over eouts) -----
// warp per (b,t) row; 8 warps / block
__global__ void k_q(const float* __restrict__ eouts) {
    __shared__ float s_w[KW * D];
    for (int i = threadIdx.x; i < KW * D; i += blockDim.x) s_w[i] = g_weff[i];
    __syncthreads();
    int warp = threadIdx.x >> 5, lane = threadIdx.x & 31;
    int row = blockIdx.x * 8 + warp;
    if (row >= B * T) return;
    const float4* e = (const float4*)(eouts + (size_t)row * D);
    float acc[KW];
    #pragma unroll
    for (int k = 0; k < KW; k++) acc[k] = 0.f;
    #pragma unroll
    for (int j = 0; j < 4; j++) {
        int idx4 = lane + 32 * j;      // 0..127 float4 per row
        float4 ev = e[idx4];
        #pragma unroll
        for (int k = 0; k < KW; k++) {
            float4 wv = ((const float4*)(s_w + k * D))[idx4];
            acc[k] += ev.x * wv.x + ev.y * wv.y + ev.z * wv.z + ev.w * wv.w;
        }
    }
    #pragma unroll
    for (int k = 0; k < KW; k++) {
        #pragma unroll
        for (int o = 16; o; o >>= 1)
            acc[k] += __shfl_down_sync(0xffffffffu, acc[k], o);
    }
    if (lane == 0) {
        #pragma unroll
        for (int k = 0; k < KW; k++) g_q[k * (B * T) + row] = acc[k];
    }
}

// ---------------- kernel 2b: banded sum + sigmoid + normalize ----------------
// one block per batch
__global__ void k_alpha(float* __restrict__ out_alpha,
                        const int* __restrict__ ylens) {
    int b = blockIdx.x;
    __shared__ float s_alpha[T];
    __shared__ float s_red[1024];
    float beff = g_beff;
    float local = 0.f;
    for (int t = threadIdx.x; t < T; t += blockDim.x) {
        float lg = beff;
        #pragma unroll
        for (int k = 0; k < KW; k++) {
            int u = t + k - KHALF;
            if (u >= 0 && u < T) lg += g_q[k * (B * T) + b * T + u];
        }
        float a = 1.f / (1.f + expf(-lg));
        s_alpha[t] = a;
        local += a;
    }
    s_red[threadIdx.x] = local;
    __syncthreads();
    for (int s = blockDim.x >> 1; s > 0; s >>= 1) {
        if (threadIdx.x < s) s_red[threadIdx.x] += s_red[threadIdx.x + s];
        __syncthreads();
    }
    float asum = s_red[0];
    float yl = (float)ylens[b];
    for (int t = threadIdx.x; t < T; t += blockDim.x) {
        float a = s_alpha[t];
        out_alpha[b * T + t] = a;
        g_anorm[b * T + t] = a / asum * yl;
    }
}

// ---------------- kernel 3a: scalar integrate-and-fire scan ------------------
// one thread per batch; emits aws sparse entries + per-token segments
__global__ void k_scan(float* __restrict__ aws,
                       const int* __restrict__ elens,
                       const int* __restrict__ ylens, int L) {
    int b = threadIdx.x;
    if (b >= B) return;
    int el = elens[b], yl = ylens[b];
    float accum = 0.f;
    int ntok = 0;
    int prev_end = -1;
    float prev_ak2 = 0.f;
    float* awb = aws + (size_t)b * (L + 1) * T;
    const float* an = g_anorm + b * T;
    for (int t = 0; t < T; t++) {
        float a = an[t];
        float t1 = accum + a;                    // alpha_accum + a_t
        bool active = (t < el) && (ntok < yl);
        bool fire = active && (t1 >= THRESH);
        float ak1 = 1.f - t1;
        float ak2 = a - ak1;
        if (fire) {
            awb[ntok * T + t] = ak1;
            awb[(ntok + 1) * T + t] = ak2;
            g_seg_s[b * MAXTOK + ntok] = prev_end;
            g_c0[b * MAXTOK + ntok] = prev_ak2;
            g_seg_e[b * MAXTOK + ntok] = t;
            g_c1[b * MAXTOK + ntok] = ak1;
            prev_end = t;
            prev_ak2 = ak2;
            ntok++;
            accum = ak2;
        } else {
            if (active) awb[ntok * T + t] = a;
            accum = t1;
        }
    }
    g_nf[b] = ntok;
}

// ---------------- kernel 3b: segmented weighted reduction -> fired -----------
// block (128 threads) per (token, batch); thread per float4 of D
__global__ void k_fired(const float* __restrict__ eouts,
                        float* __restrict__ fired, int L) {
    int b = blockIdx.y;
    int n = blockIdx.x;
    if (n >= g_nf[b]) return;
    int s = g_seg_s[b * MAXTOK + n];
    int e = g_seg_e[b * MAXTOK + n];
    float c0 = g_c0[b * MAXTOK + n];
    float c1 = g_c1[b * MAXTOK + n];
    const float* an = g_anorm + b * T;
    const float4* eb = (const float4*)(eouts + (size_t)b * T * D);
    int tid = threadIdx.x;  // 0..127
    float4 acc = make_float4(0.f, 0.f, 0.f, 0.f);
    if (s >= 0) {
        float4 v = eb[(size_t)s * 128 + tid];
        acc.x = c0 * v.x; acc.y = c0 * v.y; acc.z = c0 * v.z; acc.w = c0 * v.w;
    }
    for (int t = s + 1; t < e; t++) {
        float a = an[t];
        float4 v = eb[(size_t)t * 128 + tid];
        acc.x += a * v.x; acc.y += a * v.y; acc.z += a * v.z; acc.w += a * v.w;
    }
    {
        float4 v = eb[(size_t)e * 128 + tid];
        acc.x += c1 * v.x; acc.y += c1 * v.y; acc.z += c1 * v.z; acc.w += c1 * v.w;
    }
    ((float4*)(fired + ((size_t)b * L + n) * D))[tid] = acc;
}

// ---------------- launch ------------------------------------------------------
extern "C" void kernel_launch(void* const* d_in, const int* in_sizes, int n_in,
                              void* d_out, int out_size) {
    const float* eouts  = (const float*)d_in[0];
    const float* conv_w = (const float*)d_in[1];
    const float* conv_b = (const float*)d_in[2];
    const float* proj_w = (const float*)d_in[3];
    const float* proj_b = (const float*)d_in[4];
    const int*   elens  = (const int*)d_in[5];
    const int*   ylens  = (const int*)d_in[6];

    // out = concat(fired[B,L,D], alpha[B,T], aws[B,1,L+1,T])
    // out_size = B*L*D + B*T + B*(L+1)*T = (B*D + B*T)*L + 2*B*T
    int L = (out_size - 2 * B * T) / (B * D + B * T);

    float* out   = (float*)d_out;
    float* fired = out;
    float* alpha = out + (size_t)B * L * D;
    float* aws   = alpha + (size_t)B * T;

    cudaMemsetAsync(d_out, 0, (size_t)out_size * sizeof(float));

    // warps needed: KW*D + 1 = 5633; 8 warps per 256-thread block
    k_weff<<<(KW * D + 1 + 7) / 8, 256>>>(conv_w, conv_b, proj_w, proj_b);
    k_q<<<(B * T) / 8, 256>>>(eouts);
    k_alpha<<<B, 1024>>>(alpha, ylens);
    k_scan<<<1, 32>>>(aws, elens, ylens, L);
    k_fired<<<dim3(L, B), 128>>>(eouts, fired, L);
}

// round 2
// speedup vs baseline: 2.6363x; 2.6363x over previous
#include <cuda_runtime.h>
#include <math.h>
#include <stdint.h>

#define B 16
#define T 2048
#define D 512
#define C 512
#define KW 11
#define KHALF 5
#define THRESH 0.9f
#define MAXTOK 128

// ---------------- scratch (no allocation allowed) ----------------
__device__ float g_weff[KW * D];
__device__ float g_beff;
__device__ float g_q[KW * B * T];      // q[k][b][t] = dot(eouts[b,t,:], w_eff[k,:])
__device__ float g_anorm[B * T];       // alpha_norm
__device__ int   g_fire_t[B * MAXTOK]; // fire time of token n
__device__ float g_fak1[B * MAXTOK];   // ak1 at fire n
__device__ float g_fak2[B * MAXTOK];   // ak2 at fire n
__device__ int   g_nf[B];              // number of fired tokens per batch

// ---------------- kernel 1: fold projection into conv weights ----------------
__global__ void k_weff(const float* __restrict__ conv_w,
                       const float* __restrict__ conv_b,
                       const float* __restrict__ proj_w,
                       const float* __restrict__ proj_b) {
    int wid  = blockIdx.x * (blockDim.x >> 5) + (threadIdx.x >> 5);
    int lane = threadIdx.x & 31;
    if (wid < KW * D) {
        const float* row = conv_w + (size_t)wid * C;
        float s = 0.f;
        #pragma unroll 4
        for (int c = lane; c < C; c += 32) s += row[c] * proj_w[c];
        #pragma unroll
        for (int o = 16; o; o >>= 1) s += __shfl_down_sync(0xffffffffu, s, o);
        if (lane == 0) g_weff[wid] = s;
    } else if (wid == KW * D) {
        float s = 0.f;
        for (int c = lane; c < C; c += 32) s += conv_b[c] * proj_w[c];
        #pragma unroll
        for (int o = 16; o; o >>= 1) s += __shfl_down_sync(0xffffffffu, s, o);
        if (lane == 0) g_beff = s + proj_b[0];
    }
}

// ---------------- kernel 2a: per-timestep 11 dots (one pass over eouts) -----
__global__ void k_q(const float* __restrict__ eouts) {
    __shared__ float s_w[KW * D];
    for (int i = threadIdx.x; i < KW * D; i += blockDim.x) s_w[i] = g_weff[i];
    __syncthreads();
    int warp = threadIdx.x >> 5, lane = threadIdx.x & 31;
    int row = blockIdx.x * 8 + warp;
    if (row >= B * T) return;
    const float4* e = (const float4*)(eouts + (size_t)row * D);
    float acc[KW];
    #pragma unroll
    for (int k = 0; k < KW; k++) acc[k] = 0.f;
    #pragma unroll
    for (int j = 0; j < 4; j++) {
        int idx4 = lane + 32 * j;
        float4 ev = e[idx4];
        #pragma unroll
        for (int k = 0; k < KW; k++) {
            float4 wv = ((const float4*)(s_w + k * D))[idx4];
            acc[k] += ev.x * wv.x + ev.y * wv.y + ev.z * wv.z + ev.w * wv.w;
        }
    }
    #pragma unroll
    for (int k = 0; k < KW; k++) {
        #pragma unroll
        for (int o = 16; o; o >>= 1)
            acc[k] += __shfl_down_sync(0xffffffffu, acc[k], o);
    }
    if (lane == 0) {
        #pragma unroll
        for (int k = 0; k < KW; k++) g_q[k * (B * T) + row] = acc[k];
    }
}

// ---------------- kernel 2b+3a fused: alpha + prefix + ballot fire search ----
// one block of 1024 threads per batch
__global__ void k_alpha_scan(float* __restrict__ out_alpha,
                             float* __restrict__ aws,
                             const int* __restrict__ elens,
                             const int* __restrict__ ylens, int L) {
    int b = blockIdx.x;
    int tid = threadIdx.x;
    int lane = tid & 31, wid = tid >> 5;

    __shared__ float  sA[T];        // alpha_norm
    __shared__ double sS[T];        // inclusive prefix of alpha_norm
    __shared__ double sWarp[32];
    __shared__ int    s_fire_t[MAXTOK];
    __shared__ float  s_ak1[MAXTOK], s_ak2[MAXTOK];
    __shared__ int    s_ntok;
    __shared__ float  s_asum;

    int el = elens[b];
    int yl = ylens[b];
    float beff = g_beff;

    // --- step 1: raw sigmoid alphas + block reduce for asum (double) ---
    float a0, a1;
    {
        double local = 0.0;
        #pragma unroll
        for (int rep = 0; rep < 2; rep++) {
            int t = tid + rep * 1024;
            float lg = beff;
            #pragma unroll
            for (int k = 0; k < KW; k++) {
                int u = t + k - KHALF;
                if (u >= 0 && u < T) lg += g_q[k * (B * T) + b * T + u];
            }
            float a = 1.f / (1.f + expf(-lg));
            if (rep == 0) a0 = a; else a1 = a;
            local += (double)a;
        }
        // warp reduce
        #pragma unroll
        for (int o = 16; o; o >>= 1) local += __shfl_down_sync(0xffffffffu, local, o);
        if (lane == 0) sWarp[wid] = local;
        __syncthreads();
        if (wid == 0) {
            double v = sWarp[lane];
            #pragma unroll
            for (int o = 16; o; o >>= 1) v += __shfl_down_sync(0xffffffffu, v, o);
            if (lane == 0) s_asum = (float)v;
        }
        __syncthreads();
    }
    float asum = s_asum;
    float ylf = (float)yl;

    // --- step 2: alpha_norm (float, same elementwise formula as reference) ---
    {
        int t0 = tid, t1 = tid + 1024;
        float an0 = a0 / asum * ylf;
        float an1 = a1 / asum * ylf;
        sA[t0] = an0; sA[t1] = an1;
        out_alpha[b * T + t0] = a0;  out_alpha[b * T + t1] = a1;
        g_anorm[b * T + t0] = an0;   g_anorm[b * T + t1] = an1;
    }
    __syncthreads();

    // --- step 3: block inclusive prefix scan (double) of sA into sS ---
    {
        float e0 = sA[2 * tid], e1 = sA[2 * tid + 1];
        double my = (double)e0 + (double)e1;
        double v = my;
        #pragma unroll
        for (int o = 1; o < 32; o <<= 1) {
            double n = __shfl_up_sync(0xffffffffu, v, o);
            if (lane >= o) v += n;
        }
        if (lane == 31) sWarp[wid] = v;
        __syncthreads();
        if (wid == 0) {
            double w = sWarp[lane];
            #pragma unroll
            for (int o = 1; o < 32; o <<= 1) {
                double n = __shfl_up_sync(0xffffffffu, w, o);
                if (lane >= o) w += n;
            }
            sWarp[lane] = w;
        }
        __syncthreads();
        double base = (wid ? sWarp[wid - 1] : 0.0) + (v - my);
        sS[2 * tid]     = base + (double)e0;
        sS[2 * tid + 1] = base + (double)e0 + (double)e1;
    }
    __syncthreads();

    // --- step 4: warp 0 finds fires via monotone ballot sweep ---
    if (wid == 0) {
        double Ccorr = 0.0;
        int ntok = 0;
        int pos = 0;
        while (ntok < yl) {
            double th = (double)THRESH - Ccorr;
            int found = -1;
            for (int base = pos; base < el; base += 32) {
                int t = base + lane;
                bool hit = (t < el) && (sS[t] >= th);
                unsigned m = __ballot_sync(0xffffffffu, hit);
                if (m) { found = base + __ffs(m) - 1; break; }
            }
            if (found < 0) break;
            float a = sA[found];
            float acc = (float)(sS[found] + Ccorr);
            float ak1 = 1.f - acc;
            float ak2 = a - ak1;
            if (lane == 0) {
                s_fire_t[ntok] = found;
                s_ak1[ntok] = ak1;
                s_ak2[ntok] = ak2;
            }
            Ccorr += (double)a - 1.0;
            ntok++;
            pos = found + 1;
        }
        __syncwarp();
        if (lane == 0) { s_ntok = ntok; g_nf[b] = ntok; }
        for (int i = lane; i < ntok; i += 32) {
            g_fire_t[b * MAXTOK + i] = s_fire_t[i];
            g_fak1[b * MAXTOK + i] = s_ak1[i];
            g_fak2[b * MAXTOK + i] = s_ak2[i];
        }
    }
    __syncthreads();

    // --- step 5: fill aws in parallel ---
    int ntok = s_ntok;
    float* awb = aws + (size_t)b * (L + 1) * T;
    for (int t = tid; t < el; t += 1024) {
        // row = number of fires with fire_t < t (binary search)
        int lo = 0, hi = ntok;
        while (lo < hi) {
            int m = (lo + hi) >> 1;
            if (s_fire_t[m] < t) lo = m + 1; else hi = m;
        }
        int row = lo;
        if (row < ntok && s_fire_t[row] == t) {
            awb[row * T + t] = s_ak1[row];
            awb[(row + 1) * T + t] = s_ak2[row];
        } else if (row < yl) {
            awb[row * T + t] = sA[t];
        }
    }
}

// ---------------- kernel 3b: segmented weighted reduction -> fired -----------
__global__ void k_fired(const float* __restrict__ eouts,
                        float* __restrict__ fired, int L) {
    int b = blockIdx.y;
    int n = blockIdx.x;
    if (n >= g_nf[b]) return;
    int e = g_fire_t[b * MAXTOK + n];
    float c1 = g_fak1[b * MAXTOK + n];
    int s; float c0;
    if (n == 0) { s = -1; c0 = 0.f; }
    else { s = g_fire_t[b * MAXTOK + n - 1]; c0 = g_fak2[b * MAXTOK + n - 1]; }
    const float* an = g_anorm + b * T;
    const float4* eb = (const float4*)(eouts + (size_t)b * T * D);
    int tid = threadIdx.x;  // 0..127
    float4 acc = make_float4(0.f, 0.f, 0.f, 0.f);
    if (s >= 0) {
        float4 v = eb[(size_t)s * 128 + tid];
        acc.x = c0 * v.x; acc.y = c0 * v.y; acc.z = c0 * v.z; acc.w = c0 * v.w;
    }
    for (int t = s + 1; t < e; t++) {
        float a = an[t];
        float4 v = eb[(size_t)t * 128 + tid];
        acc.x += a * v.x; acc.y += a * v.y; acc.z += a * v.z; acc.w += a * v.w;
    }
    {
        float4 v = eb[(size_t)e * 128 + tid];
        acc.x += c1 * v.x; acc.y += c1 * v.y; acc.z += c1 * v.z; acc.w += c1 * v.w;
    }
    ((float4*)(fired + ((size_t)b * L + n) * D))[tid] = acc;
}

// ---------------- launch ------------------------------------------------------
extern "C" void kernel_launch(void* const* d_in, const int* in_sizes, int n_in,
                              void* d_out, int out_size) {
    const float* eouts  = (const float*)d_in[0];
    const float* conv_w = (const float*)d_in[1];
    const float* conv_b = (const float*)d_in[2];
    const float* proj_w = (const float*)d_in[3];
    const float* proj_b = (const float*)d_in[4];
    const int*   elens  = (const int*)d_in[5];
    const int*   ylens  = (const int*)d_in[6];

    // out = concat(fired[B,L,D], alpha[B,T], aws[B,1,L+1,T])
    int L = (out_size - 2 * B * T) / (B * D + B * T);

    float* out   = (float*)d_out;
    float* fired = out;
    float* alpha = out + (size_t)B * L * D;
    float* aws   = alpha + (size_t)B * T;

    cudaMemsetAsync(d_out, 0, (size_t)out_size * sizeof(float));

    k_weff<<<(KW * D + 1 + 7) / 8, 256>>>(conv_w, conv_b, proj_w, proj_b);
    k_q<<<(B * T) / 8, 256>>>(eouts);
    k_alpha_scan<<<B, 1024>>>(alpha, aws, elens, ylens, L);
    k_fired<<<dim3(L, B), 128>>>(eouts, fired, L);
}

// round 3
// speedup vs baseline: 3.5939x; 1.3633x over previous
#include <cuda_runtime.h>
#include <math.h>
#include <stdint.h>

#define B 16
#define T 2048
#define D 512
#define C 512
#define KW 11
#define KHALF 5
#define THRESH 0.9f
#define MAXTOK 128
#define TILE 32   // t-tile per k_logit block

// ---------------- scratch (no allocation allowed) ----------------
__device__ __align__(16) float g_weff[KW * D];
__device__ float g_beff;
__device__ float g_logit[B * T];
__device__ float g_anorm[B * T];       // alpha_norm
__device__ int   g_fire_t[B * MAXTOK]; // fire time of token n
__device__ float g_fak1[B * MAXTOK];   // ak1 at fire n
__device__ float g_fak2[B * MAXTOK];   // ak2 at fire n
__device__ int   g_nf[B];              // number of fired tokens per batch

// ---- packed f32x2 helpers (sm_103a) ----
__device__ __forceinline__ unsigned long long pack2(float a, float b) {
    unsigned long long r;
    asm("mov.b64 %0, {%1, %2};" : "=l"(r) : "f"(a), "f"(b));
    return r;
}
__device__ __forceinline__ void unpack2(unsigned long long v, float& a, float& b) {
    asm("mov.b64 {%0, %1}, %2;" : "=f"(a), "=f"(b) : "l"(v));
}
#define FMA2(accv, av, bv) \
    asm("fma.rn.f32x2 %0, %1, %2, %0;" : "+l"(accv) : "l"(av), "l"(bv))

// ---------------- kernel 1: fold projection into conv weights ----------------
__global__ void k_weff(const float* __restrict__ conv_w,
                       const float* __restrict__ conv_b,
                       const float* __restrict__ proj_w,
                       const float* __restrict__ proj_b) {
    int wid  = blockIdx.x * (blockDim.x >> 5) + (threadIdx.x >> 5);
    int lane = threadIdx.x & 31;
    if (wid < KW * D) {
        const float* row = conv_w + (size_t)wid * C;
        float s = 0.f;
        #pragma unroll 4
        for (int c = lane; c < C; c += 32) s += row[c] * proj_w[c];
        #pragma unroll
        for (int o = 16; o; o >>= 1) s += __shfl_down_sync(0xffffffffu, s, o);
        if (lane == 0) g_weff[wid] = s;
    } else if (wid == KW * D) {
        float s = 0.f;
        for (int c = lane; c < C; c += 32) s += conv_b[c] * proj_w[c];
        #pragma unroll
        for (int o = 16; o; o >>= 1) s += __shfl_down_sync(0xffffffffu, s, o);
        if (lane == 0) g_beff = s + proj_b[0];
    }
}

// ---------------- kernel 2: direct conv logits, register sliding window ------
// grid (T/TILE, B), 128 threads: thread owns float4 d-slice, weights + 32
// accumulators in registers, each eouts element loaded exactly once.
__global__ void __launch_bounds__(128, 3)
k_logit(const float* __restrict__ eouts) {
    int b = blockIdx.y;
    int t0 = blockIdx.x * TILE;
    int tid = threadIdx.x;  // 0..127

    unsigned long long w01[KW], w23[KW];
    #pragma unroll
    for (int k = 0; k < KW; k++) {
        float4 w = ((const float4*)(g_weff + k * D))[tid];
        w01[k] = pack2(w.x, w.y);
        w23[k] = pack2(w.z, w.w);
    }

    unsigned long long acc[TILE];
    unsigned long long z = pack2(0.f, 0.f);
    #pragma unroll
    for (int i = 0; i < TILE; i++) acc[i] = z;

    const float4* eb = (const float4*)(eouts + (size_t)b * T * D);
    #pragma unroll
    for (int tt = 0; tt < TILE + 2 * KHALF; tt++) {
        int t = t0 + tt - KHALF;
        float4 v = make_float4(0.f, 0.f, 0.f, 0.f);
        if (t >= 0 && t < T) v = eb[(size_t)t * (D / 4) + tid];
        unsigned long long v01 = pack2(v.x, v.y);
        unsigned long long v23 = pack2(v.z, v.w);
        #pragma unroll
        for (int k = 0; k < KW; k++) {
            int i = tt - k;             // compile-time constant per (tt,k)
            if (i >= 0 && i < TILE) {
                FMA2(acc[i], v01, w01[k]);
                FMA2(acc[i], v23, w23[k]);
            }
        }
    }

    // reduce 128 d-slices per output
    __shared__ float s[TILE][129];
    #pragma unroll
    for (int i = 0; i < TILE; i++) {
        float lo, hi;
        unpack2(acc[i], lo, hi);
        s[i][tid] = lo + hi;
    }
    __syncthreads();
    __shared__ float s2[TILE][4];
    {
        int i = tid >> 2, seg = tid & 3;
        float sum = 0.f;
        #pragma unroll
        for (int j = 0; j < 32; j++) sum += s[i][seg * 32 + j];
        s2[i][seg] = sum;
    }
    __syncthreads();
    if (tid < TILE) {
        float tot = s2[tid][0] + s2[tid][1] + s2[tid][2] + s2[tid][3] + g_beff;
        g_logit[b * T + t0 + tid] = tot;
    }
}

// ---------------- kernel 3: alpha + prefix + ballot fire search --------------
// one block of 1024 threads per batch
__global__ void k_alpha_scan(float* __restrict__ out_alpha,
                             float* __restrict__ aws,
                             const int* __restrict__ elens,
                             const int* __restrict__ ylens, int L) {
    int b = blockIdx.x;
    int tid = threadIdx.x;
    int lane = tid & 31, wid = tid >> 5;

    __shared__ float  sA[T];        // alpha_norm
    __shared__ double sS[T];        // inclusive prefix of alpha_norm
    __shared__ double sWarp[32];
    __shared__ int    s_fire_t[MAXTOK];
    __shared__ float  s_ak1[MAXTOK], s_ak2[MAXTOK];
    __shared__ int    s_ntok;
    __shared__ float  s_asum;

    int el = elens[b];
    int yl = ylens[b];

    // --- step 1: sigmoid alphas + block reduce for asum ---
    float a0, a1;
    {
        double local = 0.0;
        #pragma unroll
        for (int rep = 0; rep < 2; rep++) {
            int t = tid + rep * 1024;
            float lg = g_logit[b * T + t];
            float a = 1.f / (1.f + expf(-lg));
            if (rep == 0) a0 = a; else a1 = a;
            local += (double)a;
        }
        #pragma unroll
        for (int o = 16; o; o >>= 1) local += __shfl_down_sync(0xffffffffu, local, o);
        if (lane == 0) sWarp[wid] = local;
        __syncthreads();
        if (wid == 0) {
            double v = sWarp[lane];
            #pragma unroll
            for (int o = 16; o; o >>= 1) v += __shfl_down_sync(0xffffffffu, v, o);
            if (lane == 0) s_asum = (float)v;
        }
        __syncthreads();
    }
    float asum = s_asum;
    float ylf = (float)yl;

    // --- step 2: alpha_norm ---
    {
        int t0 = tid, t1 = tid + 1024;
        float an0 = a0 / asum * ylf;
        float an1 = a1 / asum * ylf;
        sA[t0] = an0; sA[t1] = an1;
        out_alpha[b * T + t0] = a0;  out_alpha[b * T + t1] = a1;
        g_anorm[b * T + t0] = an0;   g_anorm[b * T + t1] = an1;
    }
    __syncthreads();

    // --- step 3: block inclusive prefix scan (double) ---
    {
        float e0 = sA[2 * tid], e1 = sA[2 * tid + 1];
        double my = (double)e0 + (double)e1;
        double v = my;
        #pragma unroll
        for (int o = 1; o < 32; o <<= 1) {
            double n = __shfl_up_sync(0xffffffffu, v, o);
            if (lane >= o) v += n;
        }
        if (lane == 31) sWarp[wid] = v;
        __syncthreads();
        if (wid == 0) {
            double w = sWarp[lane];
            #pragma unroll
            for (int o = 1; o < 32; o <<= 1) {
                double n = __shfl_up_sync(0xffffffffu, w, o);
                if (lane >= o) w += n;
            }
            sWarp[lane] = w;
        }
        __syncthreads();
        double base = (wid ? sWarp[wid - 1] : 0.0) + (v - my);
        sS[2 * tid]     = base + (double)e0;
        sS[2 * tid + 1] = base + (double)e0 + (double)e1;
    }
    __syncthreads();

    // --- step 4: warp 0 finds fires via monotone ballot sweep ---
    if (wid == 0) {
        double Ccorr = 0.0;
        int ntok = 0;
        int pos = 0;
        while (ntok < yl) {
            double th = (double)THRESH - Ccorr;
            int found = -1;
            for (int base = pos; base < el; base += 32) {
                int t = base + lane;
                bool hit = (t < el) && (sS[t] >= th);
                unsigned m = __ballot_sync(0xffffffffu, hit);
                if (m) { found = base + __ffs(m) - 1; break; }
            }
            if (found < 0) break;
            float a = sA[found];
            float acc = (float)(sS[found] + Ccorr);
            float ak1 = 1.f - acc;
            float ak2 = a - ak1;
            if (lane == 0) {
                s_fire_t[ntok] = found;
                s_ak1[ntok] = ak1;
                s_ak2[ntok] = ak2;
            }
            Ccorr += (double)a - 1.0;
            ntok++;
            pos = found + 1;
        }
        __syncwarp();
        if (lane == 0) { s_ntok = ntok; g_nf[b] = ntok; }
        for (int i = lane; i < ntok; i += 32) {
            g_fire_t[b * MAXTOK + i] = s_fire_t[i];
            g_fak1[b * MAXTOK + i] = s_ak1[i];
            g_fak2[b * MAXTOK + i] = s_ak2[i];
        }
    }
    __syncthreads();

    // --- step 5: fill aws in parallel ---
    int ntok = s_ntok;
    float* awb = aws + (size_t)b * (L + 1) * T;
    for (int t = tid; t < el; t += 1024) {
        int lo = 0, hi = ntok;
        while (lo < hi) {
            int m = (lo + hi) >> 1;
            if (s_fire_t[m] < t) lo = m + 1; else hi = m;
        }
        int row = lo;
        if (row < ntok && s_fire_t[row] == t) {
            awb[row * T + t] = s_ak1[row];
            awb[(row + 1) * T + t] = s_ak2[row];
        } else if (row < yl) {
            awb[row * T + t] = sA[t];
        }
    }
}

// ---------------- kernel 4: segmented weighted reduction -> fired ------------
__global__ void __launch_bounds__(128)
k_fired(const float* __restrict__ eouts, float* __restrict__ fired, int L) {
    int b = blockIdx.y;
    int n = blockIdx.x;
    if (n >= g_nf[b]) return;
    int e = g_fire_t[b * MAXTOK + n];
    float c1 = g_fak1[b * MAXTOK + n];
    int s; float c0;
    if (n == 0) { s = -1; c0 = 0.f; }
    else { s = g_fire_t[b * MAXTOK + n - 1]; c0 = g_fak2[b * MAXTOK + n - 1]; }
    const float* an = g_anorm + b * T;
    const float4* eb = (const float4*)(eouts + (size_t)b * T * D);
    int tid = threadIdx.x;  // 0..127
    float4 acc = make_float4(0.f, 0.f, 0.f, 0.f);
    if (s >= 0) {
        float4 v = eb[(size_t)s * 128 + tid];
        acc.x = c0 * v.x; acc.y = c0 * v.y; acc.z = c0 * v.z; acc.w = c0 * v.w;
    }
    int t = s + 1;
    // unrolled x4 for MLP
    for (; t + 3 < e; t += 4) {
        float a0 = an[t], a1 = an[t + 1], a2 = an[t + 2], a3 = an[t + 3];
        float4 v0 = eb[(size_t)(t    ) * 128 + tid];
        float4 v1 = eb[(size_t)(t + 1) * 128 + tid];
        float4 v2 = eb[(size_t)(t + 2) * 128 + tid];
        float4 v3 = eb[(size_t)(t + 3) * 128 + tid];
        acc.x += a0 * v0.x; acc.y += a0 * v0.y; acc.z += a0 * v0.z; acc.w += a0 * v0.w;
        acc.x += a1 * v1.x; acc.y += a1 * v1.y; acc.z += a1 * v1.z; acc.w += a1 * v1.w;
        acc.x += a2 * v2.x; acc.y += a2 * v2.y; acc.z += a2 * v2.z; acc.w += a2 * v2.w;
        acc.x += a3 * v3.x; acc.y += a3 * v3.y; acc.z += a3 * v3.z; acc.w += a3 * v3.w;
    }
    for (; t < e; t++) {
        float a = an[t];
        float4 v = eb[(size_t)t * 128 + tid];
        acc.x += a * v.x; acc.y += a * v.y; acc.z += a * v.z; acc.w += a * v.w;
    }
    {
        float4 v = eb[(size_t)e * 128 + tid];
        acc.x += c1 * v.x; acc.y += c1 * v.y; acc.z += c1 * v.z; acc.w += c1 * v.w;
    }
    ((float4*)(fired + ((size_t)b * L + n) * D))[tid] = acc;
}

// ---------------- launch ------------------------------------------------------
extern "C" void kernel_launch(void* const* d_in, const int* in_sizes, int n_in,
                              void* d_out, int out_size) {
    const float* eouts  = (const float*)d_in[0];
    const float* conv_w = (const float*)d_in[1];
    const float* conv_b = (const float*)d_in[2];
    const float* proj_w = (const float*)d_in[3];
    const float* proj_b = (const float*)d_in[4];
    const int*   elens  = (const int*)d_in[5];
    const int*   ylens  = (const int*)d_in[6];

    // out = concat(fired[B,L,D], alpha[B,T], aws[B,1,L+1,T])
    int L = (out_size - 2 * B * T) / (B * D + B * T);

    float* out   = (float*)d_out;
    float* fired = out;
    float* alpha = out + (size_t)B * L * D;
    float* aws   = alpha + (size_t)B * T;

    cudaMemsetAsync(d_out, 0, (size_t)out_size * sizeof(float));

    k_weff<<<(KW * D + 1 + 7) / 8, 256>>>(conv_w, conv_b, proj_w, proj_b);
    k_logit<<<dim3(T / TILE, B), 128>>>(eouts);
    k_alpha_scan<<<B, 1024>>>(alpha, aws, elens, ylens, L);
    k_fired<<<dim3(L, B), 128>>>(eouts, fired, L);
}